// round 17
// baseline (speedup 1.0000x reference)
#include <cuda_runtime.h>
#include <cstdint>

#define BB 4096
#define NN 8192
#define DD 512
#define RR 4
#define NBLK (NN / 4)   // 2048 blocks, 4 warps = 4 rows per block

// Tagged partials: high 32 bits = generation tag, low 32 bits = float bits.
__device__ unsigned long long g_partial64[NBLK];  // zero-init at load
__device__ unsigned int g_gen;                    // zero-init; bumped by block 0 each run

__device__ __forceinline__ const float* row_ptr(const float* zi, const float* zj, int r) {
    return (r < BB) ? (zi + (size_t)r * DD) : (zj + (size_t)(r - BB) * DD);
}

__device__ __forceinline__ void ldg4(float4& v, const float* p) {
    asm volatile("ld.global.nc.v4.f32 {%0,%1,%2,%3}, [%4];"
                 : "=f"(v.x), "=f"(v.y), "=f"(v.z), "=f"(v.w)
                 : "l"(p));
}

// One warp per row: fused norms + 5 partner dots + NLL (round-13 body).
// Tail: ONE st.global.cg.u64 per block carrying (gen-tag | partial). No
// fences, no atomics, no release ops anywhere -> per-SM L1 stays intact
// (the 4.2us tail cost of rounds 13-16 was gpu-scope release ordering).
// Block 0 polls the tagged slots in fixed order (deterministic sum), writes
// the mean, and bumps g_gen for the next graph replay.
__global__ void __launch_bounds__(128) fused_kernel(const float* __restrict__ zi,
                                                    const float* __restrict__ zj,
                                                    const int* __restrict__ neg_idx,
                                                    float* __restrict__ out) {
    __shared__ float s_nll[4];
    __shared__ float s_ws[4];

    int warp = threadIdx.x >> 5;
    int lane = threadIdx.x & 31;
    int row  = blockIdx.x * 4 + warp;
    int col  = lane * 4;

    // Current generation (L2 read, .cg). Every block reads it BEFORE storing
    // its tag, so when block 0 has seen all 2048 tags, all reads happened.
    unsigned int gen;
    asm volatile("ld.global.cg.u32 %0, [%1];" : "=r"(gen) : "l"(&g_gen));
    unsigned int tag = gen + 1u;

    // ---- per-row work (round-13 body) ----
    int4 nv = *reinterpret_cast<const int4*>(neg_idx + row * RR);
    int part[5];
    part[0] = (row + BB) & (NN - 1);
    part[1] = nv.x + (nv.x >= row ? 1 : 0);
    part[2] = nv.y + (nv.y >= row ? 1 : 0);
    part[3] = nv.z + (nv.z >= row ? 1 : 0);
    part[4] = nv.w + (nv.w >= row ? 1 : 0);

    const float* px = row_ptr(zi, zj, row);
    float4 x[4];
#pragma unroll
    for (int k = 0; k < 4; k++) ldg4(x[k], px + col + k * 128);

    float4 y[5][4];
#pragma unroll
    for (int p = 0; p < 5; p++) {
        const float* pj = row_ptr(zi, zj, part[p]);
#pragma unroll
        for (int k = 0; k < 4; k++) ldg4(y[p][k], pj + col + k * 128);
    }

    float x2 = 0.0f;
#pragma unroll
    for (int k = 0; k < 4; k++)
        x2 += x[k].x * x[k].x + x[k].y * x[k].y + x[k].z * x[k].z + x[k].w * x[k].w;

    float dot[5], y2[5];
#pragma unroll
    for (int p = 0; p < 5; p++) {
        float d = 0.0f, n = 0.0f;
#pragma unroll
        for (int k = 0; k < 4; k++) {
            float4 a = x[k], b = y[p][k];
            d += a.x * b.x + a.y * b.y + a.z * b.z + a.w * b.w;
            n += b.x * b.x + b.y * b.y + b.z * b.z + b.w * b.w;
        }
        dot[p] = d;
        y2[p]  = n;
    }

#pragma unroll
    for (int o = 16; o; o >>= 1) {
        x2 += __shfl_xor_sync(0xFFFFFFFFu, x2, o);
#pragma unroll
        for (int p = 0; p < 5; p++) {
            dot[p] += __shfl_xor_sync(0xFFFFFFFFu, dot[p], o);
            y2[p]  += __shfl_xor_sync(0xFFFFFFFFu, y2[p], o);
        }
    }

    if (lane == 0) {
        const float invT = 1.0f / (0.5f + 1e-8f);
        float rnx = 1.0f / fmaxf(sqrtf(x2), 1e-8f);
        float l[5];
#pragma unroll
        for (int p = 0; p < 5; p++) {
            float rny = 1.0f / fmaxf(sqrtf(y2[p]), 1e-8f);
            l[p] = dot[p] * rnx * rny * invT;
        }
        float m = l[0];
#pragma unroll
        for (int p = 1; p < 5; p++) m = fmaxf(m, l[p]);
        float se = 0.0f;
#pragma unroll
        for (int p = 0; p < 5; p++) se += expf(l[p] - m);
        s_nll[warp] = m + logf(se) - l[0];
    }
    __syncthreads();

    // ---- tail: ONE tagged 8-byte store per block (weak, L2-direct) ----
    if (threadIdx.x == 0) {
        float partial = s_nll[0] + s_nll[1] + s_nll[2] + s_nll[3];
        unsigned long long pk = ((unsigned long long)tag << 32)
                              | (unsigned long long)__float_as_uint(partial);
        asm volatile("st.global.cg.u64 [%0], %1;"
                     :: "l"(&g_partial64[blockIdx.x]), "l"(pk) : "memory");
    }

    // ---- block 0: poll tagged slots in fixed order, reduce, publish ----
    if (blockIdx.x == 0) {
        float s = 0.0f;
#pragma unroll
        for (int k = 0; k < NBLK / 128; k++) {
            const unsigned long long* slot = &g_partial64[threadIdx.x + k * 128];
            unsigned long long v;
            while (true) {
                asm volatile("ld.global.cg.u64 %0, [%1];" : "=l"(v) : "l"(slot));
                if ((unsigned int)(v >> 32) == tag) break;
                __nanosleep(32);
            }
            s += __uint_as_float((unsigned int)v);
        }
#pragma unroll
        for (int o = 16; o; o >>= 1) s += __shfl_xor_sync(0xFFFFFFFFu, s, o);
        if (lane == 0) s_ws[warp] = s;
        __syncthreads();
        if (threadIdx.x == 0) {
            float tot = s_ws[0] + s_ws[1] + s_ws[2] + s_ws[3];
            out[0] = tot * (1.0f / (float)NN);
            // Publish next generation; visible to the next launch via the
            // kernel-boundary memory fence.
            asm volatile("st.global.cg.u32 [%0], %1;"
                         :: "l"(&g_gen), "r"(tag) : "memory");
        }
    }
}

extern "C" void kernel_launch(void* const* d_in, const int* in_sizes, int n_in,
                              void* d_out, int out_size) {
    const float* zi      = (const float*)d_in[0];
    const float* zj      = (const float*)d_in[1];
    const int*   neg_idx = (const int*)d_in[2];
    float* out = (float*)d_out;

    fused_kernel<<<NBLK, 128>>>(zi, zj, neg_idx, out);
}